// round 1
// baseline (speedup 1.0000x reference)
#include <cuda_runtime.h>
#include <cstdint>

// Problem constants
#define BATCH 4
#define SEQ   2048
#define DMODEL 512
#define NHEAD 8
#define HDIM  64
#define MROWS (BATCH * SEQ)          // 8192
#define QKV_N (3 * DMODEL)           // 1536

__constant__ float kScale = 0.125f;  // 1/sqrt(64)

// Scratch (device globals: allocation-free per harness rules)
__device__ float g_q[(size_t)BATCH * NHEAD * SEQ * HDIM];   // 16 MB
__device__ float g_k[(size_t)BATCH * NHEAD * SEQ * HDIM];   // 16 MB
__device__ float g_v[(size_t)BATCH * NHEAD * SEQ * HDIM];   // 16 MB
__device__ float g_ao[(size_t)BATCH * SEQ * DMODEL];        // 16 MB  (b, s, d) layout

// ---------------------------------------------------------------------------
// Tiled fp32 GEMM: C[M,N] = A[M,K] @ B[K,N] + bias[N]
// BM=BN=128, BK=8, 256 threads, 8x8 microtile per thread.
// MODE 0: QKV epilogue -> scatter into g_q/g_k/g_v (head-major).
// MODE 1: plain epilogue -> C.
// ---------------------------------------------------------------------------
template <int MODE>
__global__ __launch_bounds__(256, 2)
void gemm_kernel(const float* __restrict__ A, const float* __restrict__ Bm,
                 const float* __restrict__ bias, float* __restrict__ C,
                 int M, int N, int K) {
    constexpr int BM = 128, BN = 128, BK = 8;
    __shared__ float As[BK][BM];
    __shared__ float Bs[BK][BN];

    const int tid = threadIdx.x;
    const int m0 = blockIdx.y * BM;
    const int n0 = blockIdx.x * BN;
    const int tx = tid & 15;          // 0..15
    const int ty = tid >> 4;          // 0..15

    // A loader: 2 threads per row (each loads 4 consecutive K elements)
    const int arow  = tid >> 1;           // 0..127
    const int acol4 = (tid & 1) * 4;      // 0 or 4
    // B loader: 32 threads per K-row, each loads float4 of N
    const int brow  = tid >> 5;           // 0..7
    const int bcol4 = (tid & 31) * 4;     // 0..124

    const float* Aptr = A + (size_t)(m0 + arow) * K + acol4;
    const float* Bptr = Bm + (size_t)brow * N + n0 + bcol4;

    float acc[8][8];
#pragma unroll
    for (int i = 0; i < 8; i++)
#pragma unroll
        for (int j = 0; j < 8; j++) acc[i][j] = 0.f;

    for (int k0 = 0; k0 < K; k0 += BK) {
        float4 av = *reinterpret_cast<const float4*>(Aptr + k0);
        float4 bv = *reinterpret_cast<const float4*>(Bptr + (size_t)k0 * N);
        As[acol4 + 0][arow] = av.x;
        As[acol4 + 1][arow] = av.y;
        As[acol4 + 2][arow] = av.z;
        As[acol4 + 3][arow] = av.w;
        *reinterpret_cast<float4*>(&Bs[brow][bcol4]) = bv;
        __syncthreads();

#pragma unroll
        for (int kk = 0; kk < BK; kk++) {
            float ra[8], rb[8];
            *reinterpret_cast<float4*>(ra)     = *reinterpret_cast<const float4*>(&As[kk][ty * 8]);
            *reinterpret_cast<float4*>(ra + 4) = *reinterpret_cast<const float4*>(&As[kk][ty * 8 + 4]);
            *reinterpret_cast<float4*>(rb)     = *reinterpret_cast<const float4*>(&Bs[kk][tx * 8]);
            *reinterpret_cast<float4*>(rb + 4) = *reinterpret_cast<const float4*>(&Bs[kk][tx * 8 + 4]);
#pragma unroll
            for (int i = 0; i < 8; i++)
#pragma unroll
                for (int j = 0; j < 8; j++)
                    acc[i][j] = fmaf(ra[i], rb[j], acc[i][j]);
        }
        __syncthreads();
    }

    // Epilogue
#pragma unroll
    for (int i = 0; i < 8; i++) {
        const int row = m0 + ty * 8 + i;
#pragma unroll
        for (int j = 0; j < 8; j++) {
            const int col = n0 + tx * 8 + j;
            const float val = acc[i][j] + bias[col];
            if (MODE == 0) {
                // col in [0,1536): part (q/k/v), head, within-head dim
                const int part = col >> 9;       // /512
                const int w    = col & 511;
                const int h    = w >> 6;         // /64
                const int hd   = w & 63;
                const int bb   = row >> 11;      // /2048
                const int sidx = row & 2047;
                float* dst = (part == 0) ? g_q : (part == 1) ? g_k : g_v;
                dst[((((size_t)bb * NHEAD + h) * SEQ) + sidx) * HDIM + hd] = val;
            } else {
                C[(size_t)row * N + col] = val;
            }
        }
    }
}

// ---------------------------------------------------------------------------
// Causal flash-style attention.
// grid: (SEQ/128, BATCH*NHEAD), 128 threads; 1 thread = 1 query row.
// q row + output accumulator live in registers; K/V streamed via smem chunks.
// ---------------------------------------------------------------------------
#define QB 128
#define CK 32
#define NEG_INF (-1e30f)

__global__ __launch_bounds__(QB)
void attn_kernel() {
    const int bh  = blockIdx.y;            // 0..31
    const int qb  = blockIdx.x;            // query block
    const int tid = threadIdx.x;
    const int qi  = qb * QB + tid;         // global query row within (b,h)

    const size_t base = (size_t)bh * SEQ * HDIM;
    const float* Qbh = g_q + base;
    const float* Kbh = g_k + base;
    const float* Vbh = g_v + base;

    __shared__ float Ks[CK][HDIM];
    __shared__ float Vs[CK][HDIM];

    float qreg[HDIM];
#pragma unroll
    for (int d = 0; d < HDIM; d++) qreg[d] = Qbh[(size_t)qi * HDIM + d] * kScale;

    float m = NEG_INF, l = 0.f;
    float o[HDIM];
#pragma unroll
    for (int d = 0; d < HDIM; d++) o[d] = 0.f;

    const int nk = qb * QB + QB;  // keys needed by the last row of this block

    for (int c0 = 0; c0 < nk; c0 += CK) {
        __syncthreads();
        {
            const float4* Ksrc = reinterpret_cast<const float4*>(Kbh + (size_t)c0 * HDIM);
            const float4* Vsrc = reinterpret_cast<const float4*>(Vbh + (size_t)c0 * HDIM);
            float4* Kdst = reinterpret_cast<float4*>(&Ks[0][0]);
            float4* Vdst = reinterpret_cast<float4*>(&Vs[0][0]);
#pragma unroll
            for (int i = tid; i < CK * HDIM / 4; i += QB) {
                Kdst[i] = Ksrc[i];
                Vdst[i] = Vsrc[i];
            }
        }
        __syncthreads();

        if (c0 <= qi) {
            float sc[CK];
            float cmax = NEG_INF;
#pragma unroll
            for (int j = 0; j < CK; j++) {
                const int kg = c0 + j;
                float s = NEG_INF;
                if (kg <= qi) {
                    s = 0.f;
#pragma unroll
                    for (int d = 0; d < HDIM; d++)
                        s = fmaf(qreg[d], Ks[j][d], s);
                }
                sc[j] = s;
                cmax = fmaxf(cmax, s);
            }
            const float mn   = fmaxf(m, cmax);
            const float corr = __expf(m - mn);
            l *= corr;
#pragma unroll
            for (int d = 0; d < HDIM; d++) o[d] *= corr;
#pragma unroll
            for (int j = 0; j < CK; j++) {
                const float p = __expf(sc[j] - mn);
                l += p;
#pragma unroll
                for (int d = 0; d < HDIM; d++)
                    o[d] = fmaf(p, Vs[j][d], o[d]);
            }
            m = mn;
        }
    }

    const float inv = 1.f / l;
    const int bb = bh >> 3;   // /NHEAD
    const int h  = bh & 7;
    float* dst = g_ao + ((size_t)bb * SEQ + qi) * DMODEL + h * HDIM;
#pragma unroll
    for (int d = 0; d < HDIM; d++) dst[d] = o[d] * inv;
}

// ---------------------------------------------------------------------------
extern "C" void kernel_launch(void* const* d_in, const int* in_sizes, int n_in,
                              void* d_out, int out_size) {
    const float* x     = (const float*)d_in[0];
    const float* w_qkv = (const float*)d_in[1];
    const float* b_qkv = (const float*)d_in[2];
    const float* w_out = (const float*)d_in[3];
    const float* b_out = (const float*)d_in[4];
    float* out = (float*)d_out;

    float* gao_ptr = nullptr;
    cudaGetSymbolAddress((void**)&gao_ptr, g_ao);

    // 1) QKV projection with scatter epilogue
    {
        dim3 grid(QKV_N / 128, MROWS / 128);   // (12, 64)
        gemm_kernel<0><<<grid, 256>>>(x, w_qkv, b_qkv, nullptr, MROWS, QKV_N, DMODEL);
    }
    // 2) Causal attention
    {
        dim3 grid(SEQ / QB, BATCH * NHEAD);    // (16, 32)
        attn_kernel<<<grid, QB>>>();
    }
    // 3) Output projection
    {
        dim3 grid(DMODEL / 128, MROWS / 128);  // (4, 64)
        gemm_kernel<1><<<grid, 256>>>(gao_ptr, w_out, b_out, out, MROWS, DMODEL, DMODEL);
    }
}

// round 3
// speedup vs baseline: 3.7180x; 3.7180x over previous
#include <cuda_runtime.h>
#include <cuda_bf16.h>
#include <cstdint>

// ---------------------------------------------------------------- constants
#define BATCH 4
#define SEQ   2048
#define DMODEL 512
#define NHEAD 8
#define HDIM  64
#define MROWS 8192
#define QKV_N 1536

// scratch (device globals: allocation-free)
__device__ float g_q[(size_t)BATCH * NHEAD * SEQ * HDIM];
__device__ float g_k[(size_t)BATCH * NHEAD * SEQ * HDIM];
__device__ float g_v[(size_t)BATCH * NHEAD * SEQ * HDIM];
__device__ float g_ao[(size_t)BATCH * SEQ * DMODEL];

// ---------------------------------------------------------------- helpers
__device__ __forceinline__ uint32_t smem_u32(const void* p) {
    uint32_t a;
    asm("{ .reg .u64 t; cvta.to.shared.u64 t, %1; cvt.u32.u64 %0, t; }"
        : "=r"(a) : "l"(p));
    return a;
}

__device__ __forceinline__ void ldm_x4(uint32_t* r, uint32_t addr) {
    asm volatile("ldmatrix.sync.aligned.m8n8.x4.shared.b16 {%0,%1,%2,%3}, [%4];"
                 : "=r"(r[0]), "=r"(r[1]), "=r"(r[2]), "=r"(r[3]) : "r"(addr));
}
__device__ __forceinline__ void ldm_x4_t(uint32_t* r, uint32_t addr) {
    asm volatile("ldmatrix.sync.aligned.m8n8.x4.trans.shared.b16 {%0,%1,%2,%3}, [%4];"
                 : "=r"(r[0]), "=r"(r[1]), "=r"(r[2]), "=r"(r[3]) : "r"(addr));
}
__device__ __forceinline__ void mma16816(float* d, const uint32_t* a, const uint32_t* b) {
    asm volatile(
        "mma.sync.aligned.m16n8k16.row.col.f32.bf16.bf16.f32 "
        "{%0,%1,%2,%3}, {%4,%5,%6,%7}, {%8,%9}, {%0,%1,%2,%3};"
        : "+f"(d[0]), "+f"(d[1]), "+f"(d[2]), "+f"(d[3])
        : "r"(a[0]), "r"(a[1]), "r"(a[2]), "r"(a[3]), "r"(b[0]), "r"(b[1]));
}

// pack two floats to bf16x2 + residual bf16x2
__device__ __forceinline__ uint32_t pack_hi(float a, float b) {
    __nv_bfloat162 h = __floats2bfloat162_rn(a, b);
    return *reinterpret_cast<uint32_t*>(&h);
}
__device__ __forceinline__ uint32_t pack_lo(float a, float b, uint32_t hi) {
    __nv_bfloat162 h = *reinterpret_cast<__nv_bfloat162*>(&hi);
    float la = a - __bfloat162float(h.x);
    float lb = b - __bfloat162float(h.y);
    __nv_bfloat162 l = __floats2bfloat162_rn(la, lb);
    return *reinterpret_cast<uint32_t*>(&l);
}

// ---------------------------------------------------------------- GEMM (HMMA)
// C[M,N] = A[M,512] @ W[512,N] + bias. BM=128 BN=128 BK=32, 8 warps (4m x 2n),
// warp tile 32x64, bf16 hi/lo (3 mma per frag-pair). Double-buffered smem.
// Smem per buffer: Ahi[128][40] @0, Alo @10240, Bhi[32][136] @20480, Blo @29184.
// Buffer stride 37888; total 75776 B.
template <int MODE>
__global__ __launch_bounds__(256)
void gemm_mma(const float* __restrict__ A, const float* __restrict__ W,
              const float* __restrict__ bias, float* __restrict__ C, int N) {
    extern __shared__ char sm[];
    const uint32_t sbase = smem_u32(sm);
    const int tid = threadIdx.x, lane = tid & 31, w = tid >> 5;
    const int wm = w >> 1, wn = w & 1;
    const int m0 = blockIdx.y * 128, n0 = blockIdx.x * 128;

    float acc[2][8][4];
#pragma unroll
    for (int i = 0; i < 2; i++)
#pragma unroll
        for (int j = 0; j < 8; j++)
#pragma unroll
            for (int e = 0; e < 4; e++) acc[i][j][e] = 0.f;

    float4 aR[4], bR[4];
    const int arow = tid >> 3, ac4 = tid & 7;       // A: row within 32-row pass
    const int bkk = tid >> 5, bnn = (tid & 31) * 4; // B: k row within 8-row pass

    auto loadG = [&](int kt) {
#pragma unroll
        for (int p = 0; p < 4; p++) {
            aR[p] = *reinterpret_cast<const float4*>(
                A + (size_t)(m0 + p * 32 + arow) * 512 + kt * 32 + ac4 * 4);
            bR[p] = *reinterpret_cast<const float4*>(
                W + (size_t)(kt * 32 + p * 8 + bkk) * N + n0 + bnn);
        }
    };
    auto storeS = [&](int buf) {
        char* b = sm + buf * 37888;
#pragma unroll
        for (int p = 0; p < 4; p++) {
            const int row = p * 32 + arow;
            uint2 hv, lv;
            hv.x = pack_hi(aR[p].x, aR[p].y); lv.x = pack_lo(aR[p].x, aR[p].y, hv.x);
            hv.y = pack_hi(aR[p].z, aR[p].w); lv.y = pack_lo(aR[p].z, aR[p].w, hv.y);
            *reinterpret_cast<uint2*>(b + (row * 40 + ac4 * 4) * 2) = hv;
            *reinterpret_cast<uint2*>(b + 10240 + (row * 40 + ac4 * 4) * 2) = lv;
            const int kk = p * 8 + bkk;
            uint2 bh, bl;
            bh.x = pack_hi(bR[p].x, bR[p].y); bl.x = pack_lo(bR[p].x, bR[p].y, bh.x);
            bh.y = pack_hi(bR[p].z, bR[p].w); bl.y = pack_lo(bR[p].z, bR[p].w, bh.y);
            *reinterpret_cast<uint2*>(b + 20480 + (kk * 136 + bnn) * 2) = bh;
            *reinterpret_cast<uint2*>(b + 29184 + (kk * 136 + bnn) * 2) = bl;
        }
    };

    loadG(0);
    storeS(0);
    __syncthreads();

    for (int kt = 0; kt < 16; kt++) {
        const int cur = kt & 1;
        if (kt < 15) loadG(kt + 1);
        const uint32_t bA = sbase + cur * 37888;
#pragma unroll
        for (int ks = 0; ks < 2; ks++) {
            uint32_t ah[2][4], al[2][4];
#pragma unroll
            for (int mf = 0; mf < 2; mf++) {
                const uint32_t ra = bA +
                    ((wm * 32 + mf * 16 + (lane & 15)) * 40 + ks * 16 + (lane >> 4) * 8) * 2;
                ldm_x4(ah[mf], ra);
                ldm_x4(al[mf], ra + 10240);
            }
            uint32_t bh[4][4], bl[4][4];
#pragma unroll
            for (int g = 0; g < 4; g++) {
                const uint32_t rb = bA + 20480 +
                    ((ks * 16 + (lane & 15)) * 136 + wn * 64 + g * 16 + (lane >> 4) * 8) * 2;
                ldm_x4_t(bh[g], rb);
                ldm_x4_t(bl[g], rb + 8704);
            }
#pragma unroll
            for (int mf = 0; mf < 2; mf++)
#pragma unroll
                for (int nf = 0; nf < 8; nf++) {
                    const int g = nf >> 1, o = (nf & 1) * 2;
                    uint32_t bhf[2] = {bh[g][o], bh[g][o + 1]};
                    uint32_t blf[2] = {bl[g][o], bl[g][o + 1]};
                    mma16816(acc[mf][nf], ah[mf], bhf);
                    mma16816(acc[mf][nf], ah[mf], blf);
                    mma16816(acc[mf][nf], al[mf], bhf);
                }
        }
        if (kt < 15) storeS(cur ^ 1);
        __syncthreads();
    }

    // epilogue
#pragma unroll
    for (int mf = 0; mf < 2; mf++)
#pragma unroll
        for (int nf = 0; nf < 8; nf++) {
            const int col = n0 + wn * 64 + nf * 8 + (lane & 3) * 2;
            const float b0 = bias[col], b1 = bias[col + 1];
#pragma unroll
            for (int rr = 0; rr < 2; rr++) {
                const int row = m0 + wm * 32 + mf * 16 + (lane >> 2) + rr * 8;
                float2 v = make_float2(acc[mf][nf][rr * 2] + b0,
                                       acc[mf][nf][rr * 2 + 1] + b1);
                if (MODE == 0) {
                    const int part = col >> 9, ww = col & 511;
                    const int h = ww >> 6, hd = ww & 63;
                    const int bb = row >> 11, sidx = row & 2047;
                    float* dst = (part == 0) ? g_q : (part == 1) ? g_k : g_v;
                    *reinterpret_cast<float2*>(
                        dst + ((((size_t)bb * NHEAD + h) * SEQ) + sidx) * HDIM + hd) = v;
                } else {
                    *reinterpret_cast<float2*>(C + (size_t)row * N + col) = v;
                }
            }
        }
}

// ---------------------------------------------------------------- attention (HMMA)
// CTA = (128 q-rows, bh), 8 warps, warp = 16 q-rows. K-block = 64 keys.
// Q frags register-resident; K non-trans ldmatrix; V trans ldmatrix.
// Smem: Q stage hi@0 lo@18432 (128x72), then reused as Khi@0 Klo@9216 (64x72),
// Vhi@18432 Vlo@27648 (64x72). Total 36864 B.
__global__ __launch_bounds__(256)
void attn_mma() {
    extern __shared__ char sm[];
    const uint32_t sbase = smem_u32(sm);
    const int tid = threadIdx.x, lane = tid & 31, w = tid >> 5;
    const int qb = blockIdx.x, bh = blockIdx.y;

    const float* Qg = g_q + (size_t)bh * SEQ * HDIM + (size_t)qb * 128 * HDIM;
    const float* Kg = g_k + (size_t)bh * SEQ * HDIM;
    const float* Vg = g_v + (size_t)bh * SEQ * HDIM;

    // stage Q (scaled) as bf16 hi/lo
#pragma unroll
    for (int it = 0; it < 8; it++) {
        const int idx = it * 256 + tid;
        const int row = idx >> 4, c4 = idx & 15;
        float4 v = *reinterpret_cast<const float4*>(Qg + row * 64 + c4 * 4);
        v.x *= 0.125f; v.y *= 0.125f; v.z *= 0.125f; v.w *= 0.125f;
        uint2 hv, lv;
        hv.x = pack_hi(v.x, v.y); lv.x = pack_lo(v.x, v.y, hv.x);
        hv.y = pack_hi(v.z, v.w); lv.y = pack_lo(v.z, v.w, hv.y);
        *reinterpret_cast<uint2*>(sm + (row * 72 + c4 * 4) * 2) = hv;
        *reinterpret_cast<uint2*>(sm + 18432 + (row * 72 + c4 * 4) * 2) = lv;
    }
    __syncthreads();

    uint32_t qh[4][4], ql[4][4];
#pragma unroll
    for (int ks = 0; ks < 4; ks++) {
        const uint32_t ra = sbase +
            ((w * 16 + (lane & 15)) * 72 + ks * 16 + (lane >> 4) * 8) * 2;
        ldm_x4(qh[ks], ra);
        ldm_x4(ql[ks], ra + 18432);
    }
    __syncthreads();  // Q now in registers; smem free for K/V

    float oacc[8][4];
#pragma unroll
    for (int j = 0; j < 8; j++)
#pragma unroll
        for (int e = 0; e < 4; e++) oacc[j][e] = 0.f;
    float mrow[2] = {-1e30f, -1e30f};
    float lrow[2] = {0.f, 0.f};
    const int qi0 = qb * 128 + w * 16 + (lane >> 2);

    const int nkb = 2 * qb + 2;
    for (int kb = 0; kb < nkb; kb++) {
        const int k0 = kb * 64;
        // load K/V block as bf16 hi/lo (natural layout, 72-elem pad)
#pragma unroll
        for (int it = 0; it < 4; it++) {
            const int idx = it * 256 + tid;
            const int row = idx >> 4, c4 = idx & 15;
            float4 kv = *reinterpret_cast<const float4*>(Kg + (size_t)(k0 + row) * 64 + c4 * 4);
            float4 vv = *reinterpret_cast<const float4*>(Vg + (size_t)(k0 + row) * 64 + c4 * 4);
            uint2 hv, lv;
            hv.x = pack_hi(kv.x, kv.y); lv.x = pack_lo(kv.x, kv.y, hv.x);
            hv.y = pack_hi(kv.z, kv.w); lv.y = pack_lo(kv.z, kv.w, hv.y);
            *reinterpret_cast<uint2*>(sm + (row * 72 + c4 * 4) * 2) = hv;
            *reinterpret_cast<uint2*>(sm + 9216 + (row * 72 + c4 * 4) * 2) = lv;
            hv.x = pack_hi(vv.x, vv.y); lv.x = pack_lo(vv.x, vv.y, hv.x);
            hv.y = pack_hi(vv.z, vv.w); lv.y = pack_lo(vv.z, vv.w, hv.y);
            *reinterpret_cast<uint2*>(sm + 18432 + (row * 72 + c4 * 4) * 2) = hv;
            *reinterpret_cast<uint2*>(sm + 27648 + (row * 72 + c4 * 4) * 2) = lv;
        }
        __syncthreads();

        if (qb * 128 + w * 16 + 15 >= k0) {  // warp has at least one unmasked row
            // ---- S = Q K^T
            float sacc[8][4];
#pragma unroll
            for (int j = 0; j < 8; j++)
#pragma unroll
                for (int e = 0; e < 4; e++) sacc[j][e] = 0.f;
#pragma unroll
            for (int ks = 0; ks < 4; ks++) {
                uint32_t kh[4][4], kl[4][4];
#pragma unroll
                for (int g = 0; g < 4; g++) {
                    const uint32_t rb = sbase +
                        ((g * 16 + (lane & 15)) * 72 + ks * 16 + (lane >> 4) * 8) * 2;
                    ldm_x4(kh[g], rb);
                    ldm_x4(kl[g], rb + 9216);
                }
#pragma unroll
                for (int nf = 0; nf < 8; nf++) {
                    const int g = nf >> 1, o = nf & 1;
                    uint32_t bhf[2] = {kh[g][o], kh[g][o + 2]};
                    uint32_t blf[2] = {kl[g][o], kl[g][o + 2]};
                    mma16816(sacc[nf], qh[ks], bhf);
                    mma16816(sacc[nf], qh[ks], blf);
                    mma16816(sacc[nf], ql[ks], bhf);
                }
            }
            // ---- online softmax
            float mx[2] = {-1e30f, -1e30f};
#pragma unroll
            for (int nf = 0; nf < 8; nf++)
#pragma unroll
                for (int e = 0; e < 4; e++) {
                    const int col = k0 + nf * 8 + (lane & 3) * 2 + (e & 1);
                    const int r = e >> 1;
                    if (col > qi0 + r * 8) sacc[nf][e] = -1e30f;
                    else mx[r] = fmaxf(mx[r], sacc[nf][e]);
                }
#pragma unroll
            for (int r = 0; r < 2; r++) {
                mx[r] = fmaxf(mx[r], __shfl_xor_sync(0xffffffffu, mx[r], 1));
                mx[r] = fmaxf(mx[r], __shfl_xor_sync(0xffffffffu, mx[r], 2));
            }
            float mn[2], corr[2], sum[2] = {0.f, 0.f};
#pragma unroll
            for (int r = 0; r < 2; r++) {
                mn[r] = fmaxf(mrow[r], mx[r]);
                corr[r] = __expf(mrow[r] - mn[r]);
                mrow[r] = mn[r];
            }
#pragma unroll
            for (int nf = 0; nf < 8; nf++)
#pragma unroll
                for (int e = 0; e < 4; e++) {
                    const int r = e >> 1;
                    const float p = __expf(sacc[nf][e] - mn[r]);
                    sacc[nf][e] = p;
                    sum[r] += p;
                }
#pragma unroll
            for (int r = 0; r < 2; r++) {
                sum[r] += __shfl_xor_sync(0xffffffffu, sum[r], 1);
                sum[r] += __shfl_xor_sync(0xffffffffu, sum[r], 2);
                lrow[r] = lrow[r] * corr[r] + sum[r];
            }
#pragma unroll
            for (int nf = 0; nf < 8; nf++)
#pragma unroll
                for (int e = 0; e < 4; e++) oacc[nf][e] *= corr[e >> 1];
            // ---- PV
#pragma unroll
            for (int ks = 0; ks < 4; ks++) {
                uint32_t ph[4], pl[4];
                ph[0] = pack_hi(sacc[2 * ks][0], sacc[2 * ks][1]);
                pl[0] = pack_lo(sacc[2 * ks][0], sacc[2 * ks][1], ph[0]);
                ph[1] = pack_hi(sacc[2 * ks][2], sacc[2 * ks][3]);
                pl[1] = pack_lo(sacc[2 * ks][2], sacc[2 * ks][3], ph[1]);
                ph[2] = pack_hi(sacc[2 * ks + 1][0], sacc[2 * ks + 1][1]);
                pl[2] = pack_lo(sacc[2 * ks + 1][0], sacc[2 * ks + 1][1], ph[2]);
                ph[3] = pack_hi(sacc[2 * ks + 1][2], sacc[2 * ks + 1][3]);
                pl[3] = pack_lo(sacc[2 * ks + 1][2], sacc[2 * ks + 1][3], ph[3]);
                uint32_t vh[4][4], vl[4][4];
#pragma unroll
                for (int g = 0; g < 4; g++) {
                    const uint32_t rb = sbase + 18432 +
                        ((ks * 16 + (lane & 15)) * 72 + g * 16 + (lane >> 4) * 8) * 2;
                    ldm_x4_t(vh[g], rb);
                    ldm_x4_t(vl[g], rb + 9216);
                }
#pragma unroll
                for (int nf = 0; nf < 8; nf++) {
                    const int g = nf >> 1, o = (nf & 1) * 2;
                    uint32_t bhf[2] = {vh[g][o], vh[g][o + 1]};
                    uint32_t blf[2] = {vl[g][o], vl[g][o + 1]};
                    mma16816(oacc[nf], ph, bhf);
                    mma16816(oacc[nf], ph, blf);
                    mma16816(oacc[nf], pl, bhf);
                }
            }
        }
        __syncthreads();
    }

    // write out
    const int bb = bh >> 3, h = bh & 7;
#pragma unroll
    for (int r = 0; r < 2; r++) {
        const float inv = 1.f / lrow[r];
        const int qi = qi0 + r * 8;
        float* dst = g_ao + ((size_t)bb * SEQ + qi) * DMODEL + h * HDIM;
#pragma unroll
        for (int nf = 0; nf < 8; nf++) {
            const int hd = nf * 8 + (lane & 3) * 2;
            *reinterpret_cast<float2*>(dst + hd) =
                make_float2(oacc[nf][r * 2] * inv, oacc[nf][r * 2 + 1] * inv);
        }
    }
}

// ---------------------------------------------------------------- launch
extern "C" void kernel_launch(void* const* d_in, const int* in_sizes, int n_in,
                              void* d_out, int out_size) {
    const float* x     = (const float*)d_in[0];
    const float* w_qkv = (const float*)d_in[1];
    const float* b_qkv = (const float*)d_in[2];
    const float* w_out = (const float*)d_in[3];
    const float* b_out = (const float*)d_in[4];
    float* out = (float*)d_out;

    float* gao_ptr = nullptr;
    cudaGetSymbolAddress((void**)&gao_ptr, g_ao);

    const int SMEM_GEMM = 75776;
    const int SMEM_ATT  = 36864;
    cudaFuncSetAttribute(gemm_mma<0>, cudaFuncAttributeMaxDynamicSharedMemorySize, SMEM_GEMM);
    cudaFuncSetAttribute(gemm_mma<1>, cudaFuncAttributeMaxDynamicSharedMemorySize, SMEM_GEMM);
    cudaFuncSetAttribute(attn_mma,    cudaFuncAttributeMaxDynamicSharedMemorySize, SMEM_ATT);

    gemm_mma<0><<<dim3(QKV_N / 128, MROWS / 128), 256, SMEM_GEMM>>>(x, w_qkv, b_qkv, nullptr, QKV_N);
    attn_mma<<<dim3(SEQ / 128, BATCH * NHEAD), 256, SMEM_ATT>>>();
    gemm_mma<1><<<dim3(DMODEL / 128, MROWS / 128), 256, SMEM_GEMM>>>(gao_ptr, w_out, b_out, out, DMODEL);
}